// round 6
// baseline (speedup 1.0000x reference)
#include <cuda_runtime.h>
#include <cuda_fp16.h>
#include <cstdint>

// ---------------- problem constants ----------------
#define B       64
#define N       4096
#define D       64
#define H       128
#define NS      8
#define ITERS   3
#define EPSA    1e-8f
#define LN_EPS  1e-5f
#define SCALE   0.125f

#define TILE_R  64              // rows per region in kv kernel
#define NB      16              // chunks per batch in attention (256 rows each)
#define DSTR    257             // padded stride for dots/att smem

typedef unsigned long long ull;

// ---------------- device scratch ----------------
__device__ float  g_k[B*N*D];          // compacted per 64-row region
__device__ float  g_v[B*N*D];
__device__ int    g_cnt[B*N/TILE_R];   // active rows per region
__device__ float  g_slots[B*NS*D];
__device__ float  g_q[B*NS*D];
__device__ float  g_Pp[B*NB*NS*D];
__device__ float  g_Sp[B*NB*NS];
__device__ unsigned g_ctr[B];          // per-batch completion counters (self-resetting)
__device__ ulonglong2 g_wk2v[16*64];   // [d4][c] packed f32x2 pairs
__device__ ulonglong2 g_wv2v[16*64];
__device__ float4 g_WgA[64*64];        // [d][dd] = (Wih_r, Wih_z, Wih_n, Whh_r)
__device__ float2 g_WgB[64*64];        // [d][dd] = (Whh_z, Whh_n)
__device__ float2 g_W1p[64*64];        // [d][h2]
__device__ float2 g_W2p[64*64];        // [h2][dd]
__device__ float2 g_Wqp[32*64];        // [d2][dd]

// ---------------- f32x2 helpers ----------------
__device__ __forceinline__ ull packf2(float x, float y) {
    ull r;
    asm("mov.b64 %0, {%1,%2};" : "=l"(r) : "f"(x), "f"(y));
    return r;
}
__device__ __forceinline__ float2 unpackf2(ull v) {
    float2 f;
    asm("mov.b64 {%0,%1}, %2;" : "=f"(f.x), "=f"(f.y) : "l"(v));
    return f;
}
__device__ __forceinline__ ull ffma2(ull a, ull b, ull c) {
    ull d;
    asm("fma.rn.f32x2 %0, %1, %2, %3;" : "=l"(d) : "l"(a), "l"(b), "l"(c));
    return d;
}

// ---------------- prep ----------------
__global__ void k_prep(const float* __restrict__ Wk, const float* __restrict__ Wv,
                       const float* __restrict__ W_ih, const float* __restrict__ W_hh,
                       const float* __restrict__ W1, const float* __restrict__ W2,
                       const float* __restrict__ Wq) {
    int i = blockIdx.x * 256 + threadIdx.x;
    if (i < 1024) {
        int d4 = i >> 6, c = i & 63;
        float4 fk = *(const float4*)(Wk + c*64 + d4*4);
        float4 fv = *(const float4*)(Wv + c*64 + d4*4);
        ulonglong2 k2, v2;
        k2.x = packf2(fk.x, fk.y); k2.y = packf2(fk.z, fk.w);
        v2.x = packf2(fv.x, fv.y); v2.y = packf2(fv.z, fv.w);
        g_wk2v[i] = k2;
        g_wv2v[i] = v2;
    }
    if (i < 4096) {
        int d = i >> 6, x = i & 63;
        g_WgA[i] = make_float4(W_ih[x*64 + d], W_ih[(64+x)*64 + d],
                               W_ih[(128+x)*64 + d], W_hh[x*64 + d]);
        g_WgB[i] = make_float2(W_hh[(64+x)*64 + d], W_hh[(128+x)*64 + d]);
        g_W1p[i] = make_float2(W1[(2*x)*64 + d], W1[(2*x+1)*64 + d]);
        g_W2p[i] = make_float2(W2[x*128 + 2*d], W2[x*128 + 2*d + 1]);
    }
    if (i < 2048) {
        int d2 = i >> 6, dd = i & 63;
        g_Wqp[i] = make_float2(Wq[dd*64 + 2*d2], Wq[dd*64 + 2*d2 + 1]);
    }
}

// ---------------- K1: mask-compact + LN + k/v GEMM ----------------
__global__ __launch_bounds__(256, 4)
void k_ln_kv(const float* __restrict__ inputs, const int* __restrict__ mask,
             const float* __restrict__ bk, const float* __restrict__ bv,
             const float* __restrict__ lnw, const float* __restrict__ lnb) {
    __shared__ __align__(16) float xs[TILE_R*64];
    __shared__ int tpos[TILE_R];
    __shared__ int cmap[TILE_R];
    __shared__ int wc[2];

    int tid = threadIdx.x;
    int lane = tid & 31, warp = tid >> 5;
    size_t row0 = (size_t)blockIdx.x * TILE_R;

    if (tid < 64) {
        int mm = mask[row0 + tid] != 0;
        unsigned bal = __ballot_sync(~0u, mm);
        if (lane == 0) wc[warp] = __popc(bal);
        tpos[tid] = mm ? __popc(bal & ((1u << lane) - 1u)) : -1;
    }
    __syncthreads();
    int act = wc[0] + wc[1];
    if (tid < 64 && tpos[tid] >= 0)
        cmap[tpos[tid] + (tid >= 32 ? wc[0] : 0)] = tid;
    if (tid == 0) g_cnt[blockIdx.x] = act;
    __syncthreads();

    {
        float lw0 = lnw[lane], lw1 = lnw[lane+32];
        float lb0 = lnb[lane], lb1 = lnb[lane+32];
        for (int ci = warp; ci < act; ci += 8) {
            int r = cmap[ci];
            const float* src = inputs + (row0 + r)*64;
            float v0 = src[lane], v1 = src[lane+32];
            float s = v0 + v1;
            #pragma unroll
            for (int o = 16; o; o >>= 1) s += __shfl_xor_sync(~0u, s, o);
            float mu = s * (1.f/64.f);
            float d0 = v0 - mu, d1 = v1 - mu;
            float q = d0*d0 + d1*d1;
            #pragma unroll
            for (int o = 16; o; o >>= 1) q += __shfl_xor_sync(~0u, q, o);
            float rs = rsqrtf(q * (1.f/64.f) + LN_EPS);
            xs[ci*64 + lane]      = d0*rs*lw0 + lb0;
            xs[ci*64 + 32 + lane] = d1*rs*lw1 + lb1;
        }
    }
    __syncthreads();

    int c  = tid & 63;
    int rb = tid >> 6;
    float bkc = bk[c], bvc = bv[c];
    const ulonglong2* xs2 = reinterpret_cast<const ulonglong2*>(xs);
    int G = (act + 31) >> 5;
    for (int g = 0; g < G; ++g) {
        ull ak[8], av[8];
        #pragma unroll
        for (int t = 0; t < 8; ++t) { ak[t] = 0ull; av[t] = 0ull; }
        #pragma unroll
        for (int d4 = 0; d4 < 16; ++d4) {
            ulonglong2 wk = __ldg(g_wk2v + d4*64 + c);
            ulonglong2 wv = __ldg(g_wv2v + d4*64 + c);
            #pragma unroll
            for (int t = 0; t < 8; ++t) {
                int ci = g*32 + rb + 4*t;
                ulonglong2 x = xs2[ci*16 + d4];
                ak[t] = ffma2(x.x, wk.x, ak[t]);
                ak[t] = ffma2(x.y, wk.y, ak[t]);
                av[t] = ffma2(x.x, wv.x, av[t]);
                av[t] = ffma2(x.y, wv.y, av[t]);
            }
        }
        #pragma unroll
        for (int t = 0; t < 8; ++t) {
            int ci = g*32 + rb + 4*t;
            if (ci < act) {
                float2 k2 = unpackf2(ak[t]);
                float2 v2 = unpackf2(av[t]);
                g_k[(row0 + ci)*64 + c] = k2.x + k2.y + bkc;
                g_v[(row0 + ci)*64 + c] = v2.x + v2.y + bvc;
            }
        }
    }
    // rows [act, pad8) are never written -> stay zero (bss), safe for padded attn loops
}

// ---------------- LN over slot rows ----------------
__device__ __forceinline__ void lnrows(const float* in, float* out,
                                       const float* __restrict__ w,
                                       const float* __restrict__ bia, int tid, int nrows) {
    int wp = tid >> 5, lane = tid & 31;
    if (wp >= nrows) return;
    const float* p = in + wp*64;
    float v0 = p[lane], v1 = p[lane+32];
    float s = v0 + v1;
    #pragma unroll
    for (int o = 16; o; o >>= 1) s += __shfl_xor_sync(~0u, s, o);
    float mu = s * (1.f/64.f);
    float d0 = v0 - mu, d1 = v1 - mu;
    float q = d0*d0 + d1*d1;
    #pragma unroll
    for (int o = 16; o; o >>= 1) q += __shfl_xor_sync(~0u, q, o);
    float rs = rsqrtf(q * (1.f/64.f) + LN_EPS);
    out[wp*64 + lane]      = d0*rs*w[lane] + bia[lane];
    out[wp*64 + lane + 32] = d1*rs*w[lane+32] + bia[lane+32];
}

// ---------------- init ----------------
__global__ __launch_bounds__(256)
void k_init(const float* __restrict__ noise, const float* __restrict__ mu,
            const float* __restrict__ sg,
            const float* __restrict__ ln_s_w, const float* __restrict__ ln_s_b,
            const float* __restrict__ bq) {
    __shared__ float sl[512], sn[512];
    int b = blockIdx.x, tid = threadIdx.x;
    #pragma unroll
    for (int u = 0; u < 2; ++u) {
        int t = tid + 256*u, dd = t & 63;
        float s = mu[dd] + sg[dd]*noise[b*512 + t];
        sl[t] = s;
        g_slots[b*512 + t] = s;
    }
    __syncthreads();
    lnrows(sl, sn, ln_s_w, ln_s_b, tid, 8);
    __syncthreads();
    #pragma unroll
    for (int u = 0; u < 2; ++u) {
        int t = tid + 256*u, j = t >> 6, dd = t & 63;
        float acc = bq[dd];
        const float2* sj2 = (const float2*)(sn + j*64);
        #pragma unroll 8
        for (int d2 = 0; d2 < 32; ++d2) {
            float2 w = g_Wqp[d2*64 + dd];
            float2 s2 = sj2[d2];
            acc += s2.x*w.x + s2.y*w.y;
        }
        g_q[b*512 + t] = acc * SCALE;
    }
}

// ---------------- fused attention + (last block) slot update ----------------
__global__ __launch_bounds__(256)
void k_attn(const float* __restrict__ b_ih, const float* __restrict__ b_hh,
            const float* __restrict__ b1, const float* __restrict__ b2,
            const float* __restrict__ ln_ff_w, const float* __restrict__ ln_ff_b,
            const float* __restrict__ ln_s_w, const float* __restrict__ ln_s_b,
            const float* __restrict__ bq,
            float* __restrict__ d_out, int last) {
    // one buffer, two overlays:
    //  attention phase: dots[8*DSTR] | att[8*DSTR] | redP[4096] | redS[64]
    //  update phase   : upd[512] prev[512] snew[512] ffs[512] hid[1024] sfin[512] Ssm[8]
    __shared__ float sbuf[2*8*DSTR + 4096 + 64];
    __shared__ int   cnts[4];
    __shared__ int   lastFlag;

    float* dots = sbuf;
    float* att  = sbuf + 8*DSTR;
    float* redP = sbuf + 2*8*DSTR;
    float* redS = redP + 4096;

    int b = blockIdx.y, chunk = blockIdx.x;
    int tid = threadIdx.x;
    int warp = tid >> 5, lane = tid & 31;
    int jj = lane & 7;
    int gg = lane >> 3;

    if (tid < 4) cnts[tid] = g_cnt[b*(N/TILE_R) + chunk*4 + tid];

    ull q2[8];
    {
        const float4* qp = (const float4*)(g_q + b*512 + jj*64) + (gg << 2);
        #pragma unroll
        for (int i = 0; i < 4; ++i) {
            float4 t4 = qp[i];
            q2[2*i]   = packf2(t4.x, t4.y);
            q2[2*i+1] = packf2(t4.z, t4.w);
        }
    }
    __syncthreads();

    // Phase A: dots via f32x2
    #pragma unroll
    for (int s = 0; s < 4; ++s) {
        int nit = (cnts[s] + 7) >> 3;
        const float* kb = g_k + ((size_t)(b*(N/TILE_R) + chunk*4 + s) * TILE_R) * 64;
        #pragma unroll 2
        for (int it = 0; it < nit; ++it) {
            int r = it*8 + warp;
            const ulonglong2* kp = (const ulonglong2*)(kb + r*64) + (gg << 2);
            ulonglong2 x0 = kp[0], x1 = kp[1], x2 = kp[2], x3 = kp[3];
            ull acc = 0ull;
            acc = ffma2(x0.x, q2[0], acc); acc = ffma2(x0.y, q2[1], acc);
            acc = ffma2(x1.x, q2[2], acc); acc = ffma2(x1.y, q2[3], acc);
            acc = ffma2(x2.x, q2[4], acc); acc = ffma2(x2.y, q2[5], acc);
            acc = ffma2(x3.x, q2[6], acc); acc = ffma2(x3.y, q2[7], acc);
            float2 f = unpackf2(acc);
            float d = f.x + f.y;
            d += __shfl_xor_sync(~0u, d, 8);
            d += __shfl_xor_sync(~0u, d, 16);
            if (gg == 0) dots[jj*DSTR + s*64 + r] = d;
        }
    }
    __syncthreads();

    // Phase B: in-thread softmax, zero att on pad rows
    {
        int s = tid >> 6, r = tid & 63;
        int act = cnts[s];
        int pad8 = (act + 7) & ~7;
        if (r < act) {
            float d[8];
            #pragma unroll
            for (int j = 0; j < 8; ++j) d[j] = dots[j*DSTR + tid];
            float m = d[0];
            #pragma unroll
            for (int j = 1; j < 8; ++j) m = fmaxf(m, d[j]);
            float e[8], sum = 0.f;
            #pragma unroll
            for (int j = 0; j < 8; ++j) { e[j] = __expf(d[j] - m); sum += e[j]; }
            float inv = __fdividef(1.f, sum);
            #pragma unroll
            for (int j = 0; j < 8; ++j) att[j*DSTR + tid] = e[j]*inv + EPSA;
        } else if (r < pad8) {
            #pragma unroll
            for (int j = 0; j < 8; ++j) att[j*DSTR + tid] = 0.f;
        }
    }
    __syncthreads();

    // Phase C: P accumulation via f32x2
    ull P2[8];
    #pragma unroll
    for (int i = 0; i < 8; ++i) P2[i] = 0ull;
    float S = 0.f;
    #pragma unroll
    for (int s = 0; s < 4; ++s) {
        int nit = (cnts[s] + 7) >> 3;
        const float* vb = g_v + ((size_t)(b*(N/TILE_R) + chunk*4 + s) * TILE_R) * 64;
        #pragma unroll 2
        for (int it = 0; it < nit; ++it) {
            int r = it*8 + warp;
            float a = att[jj*DSTR + s*64 + r];
            S += a;
            ull a2 = packf2(a, a);
            const ulonglong2* vp = (const ulonglong2*)(vb + r*64) + (gg << 2);
            ulonglong2 x0 = vp[0], x1 = vp[1], x2 = vp[2], x3 = vp[3];
            P2[0] = ffma2(x0.x, a2, P2[0]); P2[1] = ffma2(x0.y, a2, P2[1]);
            P2[2] = ffma2(x1.x, a2, P2[2]); P2[3] = ffma2(x1.y, a2, P2[3]);
            P2[4] = ffma2(x2.x, a2, P2[4]); P2[5] = ffma2(x2.y, a2, P2[5]);
            P2[6] = ffma2(x3.x, a2, P2[6]); P2[7] = ffma2(x3.y, a2, P2[7]);
        }
    }

    float* rp = redP + warp*512 + jj*64 + (gg << 4);
    #pragma unroll
    for (int i = 0; i < 4; ++i) {
        float2 f0 = unpackf2(P2[2*i]), f1 = unpackf2(P2[2*i+1]);
        *(float4*)(rp + 4*i) = make_float4(f0.x, f0.y, f1.x, f1.y);
    }
    if (gg == 0) redS[warp*8 + jj] = S;
    __syncthreads();

    #pragma unroll
    for (int u = 0; u < 2; ++u) {
        int t = tid + 256*u;
        float s = 0.f;
        #pragma unroll
        for (int w = 0; w < 8; ++w) s += redP[w*512 + t];
        g_Pp[((size_t)b*NB + chunk)*512 + t] = s;
    }
    if (tid < 8) {
        float s = 0.f;
        #pragma unroll
        for (int w = 0; w < 8; ++w) s += redS[w*8 + tid];
        g_Sp[(b*NB + chunk)*8 + tid] = s;
    }

    // ---- last block of this batch performs the slot update ----
    __threadfence();
    __syncthreads();          // all epilogue smem reads done; sbuf reusable
    if (tid == 0) {
        unsigned c = atomicAdd(&g_ctr[b], 1u);
        lastFlag = (c == NB - 1);
        if (c == NB - 1) g_ctr[b] = 0;     // self-reset for next launch/replay
    }
    __syncthreads();
    if (!lastFlag) return;

    // update-phase smem overlay
    float* upd  = sbuf;
    float* prev = sbuf + 512;
    float* snew = sbuf + 1024;
    float* ffs  = sbuf + 1536;
    float* hid  = sbuf + 2048;   // 1024
    float* sfin = sbuf + 3072;
    float* Ssm  = sbuf + 3584;   // 8

    if (tid < 8) {
        float s = 0.f;
        const float* sp = g_Sp + b*NB*8 + tid;
        #pragma unroll
        for (int p = 0; p < NB; ++p) s += sp[p*8];
        Ssm[tid] = s;
    }
    float pr0, pr1;
    {
        float s0 = 0.f, s1 = 0.f;
        const float* pp = g_Pp + (size_t)b*NB*512;
        #pragma unroll
        for (int p = 0; p < NB; ++p) {
            s0 += pp[p*512 + tid];
            s1 += pp[p*512 + 256 + tid];
        }
        pr0 = s0; pr1 = s1;
        prev[tid]       = g_slots[b*512 + tid];
        prev[tid + 256] = g_slots[b*512 + 256 + tid];
    }
    __syncthreads();
    upd[tid]       = pr0 / Ssm[tid >> 6];
    upd[tid + 256] = pr1 / Ssm[(tid + 256) >> 6];
    __syncthreads();

    // GRU
    #pragma unroll
    for (int u = 0; u < 2; ++u) {
        int t = tid + 256*u, j = t >> 6, dd = t & 63;
        const float* uj = upd + j*64;
        const float* hj = prev + j*64;
        float xr = b_ih[dd], xz = b_ih[64+dd], xn = b_ih[128+dd];
        float hr = b_hh[dd], hz = b_hh[64+dd], hn = b_hh[128+dd];
        #pragma unroll 8
        for (int d = 0; d < 64; ++d) {
            float uu = uj[d], hh = hj[d];
            float4 wa = __ldg(g_WgA + d*64 + dd);
            float2 wb = __ldg(g_WgB + d*64 + dd);
            xr += uu*wa.x; xz += uu*wa.y; xn += uu*wa.z;
            hr += hh*wa.w; hz += hh*wb.x; hn += hh*wb.y;
        }
        float rg = 1.f/(1.f + __expf(-(xr + hr)));
        float zg = 1.f/(1.f + __expf(-(xz + hz)));
        float t2 = __expf(2.f*(xn + rg*hn));
        float nn = 1.f - 2.f/(t2 + 1.f);
        snew[t] = (1.f - zg)*nn + zg*prev[t];
    }
    __syncthreads();
    lnrows(snew, ffs, ln_ff_w, ln_ff_b, tid, 8);
    __syncthreads();
    // MLP layer 1
    #pragma unroll
    for (int u = 0; u < 2; ++u) {
        int t = tid + 256*u, j = t >> 6, h2 = t & 63;
        float a0 = b1[2*h2], a1 = b1[2*h2+1];
        const float* fj = ffs + j*64;
        #pragma unroll 8
        for (int d = 0; d < 64; ++d) {
            float2 w = __ldg(g_W1p + d*64 + h2);
            float f = fj[d];
            a0 += f*w.x; a1 += f*w.y;
        }
        hid[j*128 + 2*h2]   = fmaxf(a0, 0.f);
        hid[j*128 + 2*h2+1] = fmaxf(a1, 0.f);
    }
    __syncthreads();
    #pragma unroll
    for (int u = 0; u < 2; ++u) {
        int t = tid + 256*u, j = t >> 6, dd = t & 63;
        float acc = b2[dd];
        const float2* hj2 = (const float2*)(hid + j*128);
        #pragma unroll 8
        for (int h2 = 0; h2 < 64; ++h2) {
            float2 w = __ldg(g_W2p + h2*64 + dd);
            float2 hv = hj2[h2];
            acc += hv.x*w.x + hv.y*w.y;
        }
        float o = snew[t] + acc;
        sfin[t] = o;
        g_slots[b*512 + t] = o;
        if (last) d_out[b*512 + t] = o;
    }
    if (!last) {
        __syncthreads();
        lnrows(sfin, ffs, ln_s_w, ln_s_b, tid, 8);
        __syncthreads();
        #pragma unroll
        for (int u = 0; u < 2; ++u) {
            int t = tid + 256*u, j = t >> 6, dd = t & 63;
            float acc = bq[dd];
            const float2* sj2 = (const float2*)(ffs + j*64);
            #pragma unroll 8
            for (int d2 = 0; d2 < 32; ++d2) {
                float2 w = __ldg(g_Wqp + d2*64 + dd);
                float2 s2 = sj2[d2];
                acc += s2.x*w.x + s2.y*w.y;
            }
            g_q[b*512 + t] = acc * SCALE;
        }
    }
}

// ---------------- launch ----------------
extern "C" void kernel_launch(void* const* d_in, const int* in_sizes, int n_in,
                              void* d_out, int out_size) {
    const float* inputs     = (const float*)d_in[0];
    const int*   mask       = (const int*)  d_in[1];
    const float* noise      = (const float*)d_in[2];
    const float* slots_mu   = (const float*)d_in[3];
    const float* slots_sig  = (const float*)d_in[4];
    const float* Wq         = (const float*)d_in[5];
    const float* bq         = (const float*)d_in[6];
    const float* Wk         = (const float*)d_in[7];
    const float* bk         = (const float*)d_in[8];
    const float* Wv         = (const float*)d_in[9];
    const float* bv         = (const float*)d_in[10];
    const float* W_ih       = (const float*)d_in[11];
    const float* b_ih       = (const float*)d_in[12];
    const float* W_hh       = (const float*)d_in[13];
    const float* b_hh       = (const float*)d_in[14];
    const float* W1         = (const float*)d_in[15];
    const float* b1         = (const float*)d_in[16];
    const float* W2         = (const float*)d_in[17];
    const float* b2         = (const float*)d_in[18];
    const float* ln_in_w    = (const float*)d_in[19];
    const float* ln_in_b    = (const float*)d_in[20];
    const float* ln_s_w     = (const float*)d_in[21];
    const float* ln_s_b     = (const float*)d_in[22];
    const float* ln_ff_w    = (const float*)d_in[23];
    const float* ln_ff_b    = (const float*)d_in[24];
    float* out = (float*)d_out;

    k_prep<<<48, 256>>>(Wk, Wv, W_ih, W_hh, W1, W2, Wq);
    k_ln_kv<<<(B*N)/TILE_R, 256>>>(inputs, mask, bk, bv, ln_in_w, ln_in_b);
    k_init<<<B, 256>>>(noise, slots_mu, slots_sig, ln_s_w, ln_s_b, bq);
    for (int it = 0; it < ITERS; ++it) {
        k_attn<<<dim3(NB, B), 256>>>(b_ih, b_hh, b1, b2, ln_ff_w, ln_ff_b,
                                     ln_s_w, ln_s_b, bq, out, it == ITERS-1 ? 1 : 0);
    }
}

// round 7
// speedup vs baseline: 1.6267x; 1.6267x over previous
#include <cuda_runtime.h>
#include <cstdint>

// ---------------- problem constants ----------------
#define B       64
#define N       4096
#define D       64
#define H       128
#define NS      8
#define ITERS   3
#define EPSA    1e-8f
#define LN_EPS  1e-5f
#define SCALE   0.125f

#define TILE_R  64              // rows per region in kv kernel
#define NB      16              // chunks per batch in attention (256 rows each)
#define DSTR    257             // padded stride for dots/att smem

typedef unsigned long long ull;

// ---------------- device scratch ----------------
__device__ float  g_k[B*N*D];          // compacted per 64-row region
__device__ float  g_v[B*N*D];
__device__ int    g_cnt[B*N/TILE_R];   // active rows per region
__device__ float  g_slots[B*NS*D];
__device__ float  g_q[B*NS*D];
__device__ float  g_Pp[B*NB*NS*D];
__device__ float  g_Sp[B*NB*NS];
__device__ ulonglong2 g_wk2v[16*64];   // [d4][c] packed f32x2 pairs
__device__ ulonglong2 g_wv2v[16*64];
__device__ float4 g_WgA[64*64];        // [d][dd] = (Wih_r, Wih_z, Wih_n, Whh_r)
__device__ float2 g_WgB[64*64];        // [d][dd] = (Whh_z, Whh_n)
__device__ float2 g_W1p[64*64];        // [d][h2]
__device__ float2 g_W2p[64*64];        // [h2][dd]
__device__ float2 g_Wqp[32*64];        // [d2][dd]

// ---------------- f32x2 helpers ----------------
__device__ __forceinline__ ull packf2(float x, float y) {
    ull r;
    asm("mov.b64 %0, {%1,%2};" : "=l"(r) : "f"(x), "f"(y));
    return r;
}
__device__ __forceinline__ float2 unpackf2(ull v) {
    float2 f;
    asm("mov.b64 {%0,%1}, %2;" : "=f"(f.x), "=f"(f.y) : "l"(v));
    return f;
}
__device__ __forceinline__ ull ffma2(ull a, ull b, ull c) {
    ull d;
    asm("fma.rn.f32x2 %0, %1, %2, %3;" : "=l"(d) : "l"(a), "l"(b), "l"(c));
    return d;
}

// ---------------- prep ----------------
__global__ void k_prep(const float* __restrict__ Wk, const float* __restrict__ Wv,
                       const float* __restrict__ W_ih, const float* __restrict__ W_hh,
                       const float* __restrict__ W1, const float* __restrict__ W2,
                       const float* __restrict__ Wq) {
    int i = blockIdx.x * 256 + threadIdx.x;
    if (i < 1024) {
        int d4 = i >> 6, c = i & 63;
        float4 fk = *(const float4*)(Wk + c*64 + d4*4);
        float4 fv = *(const float4*)(Wv + c*64 + d4*4);
        ulonglong2 k2, v2;
        k2.x = packf2(fk.x, fk.y); k2.y = packf2(fk.z, fk.w);
        v2.x = packf2(fv.x, fv.y); v2.y = packf2(fv.z, fv.w);
        g_wk2v[i] = k2;
        g_wv2v[i] = v2;
    }
    if (i < 4096) {
        int d = i >> 6, x = i & 63;
        g_WgA[i] = make_float4(W_ih[x*64 + d], W_ih[(64+x)*64 + d],
                               W_ih[(128+x)*64 + d], W_hh[x*64 + d]);
        g_WgB[i] = make_float2(W_hh[(64+x)*64 + d], W_hh[(128+x)*64 + d]);
        g_W1p[i] = make_float2(W1[(2*x)*64 + d], W1[(2*x+1)*64 + d]);
        g_W2p[i] = make_float2(W2[x*128 + 2*d], W2[x*128 + 2*d + 1]);
    }
    if (i < 2048) {
        int d2 = i >> 6, dd = i & 63;
        g_Wqp[i] = make_float2(Wq[dd*64 + 2*d2], Wq[dd*64 + 2*d2 + 1]);
    }
}

// ---------------- K1: mask-compact + LN + k/v GEMM ----------------
__global__ __launch_bounds__(256, 4)
void k_ln_kv(const float* __restrict__ inputs, const int* __restrict__ mask,
             const float* __restrict__ bk, const float* __restrict__ bv,
             const float* __restrict__ lnw, const float* __restrict__ lnb) {
    __shared__ __align__(16) float xs[TILE_R*64];
    __shared__ int tpos[TILE_R];
    __shared__ int cmap[TILE_R];
    __shared__ int wc[2];

    int tid = threadIdx.x;
    int lane = tid & 31, warp = tid >> 5;
    size_t row0 = (size_t)blockIdx.x * TILE_R;

    if (tid < 64) {
        int mm = mask[row0 + tid] != 0;
        unsigned bal = __ballot_sync(~0u, mm);
        if (lane == 0) wc[warp] = __popc(bal);
        tpos[tid] = mm ? __popc(bal & ((1u << lane) - 1u)) : -1;
    }
    __syncthreads();
    int act = wc[0] + wc[1];
    if (tid < 64 && tpos[tid] >= 0)
        cmap[tpos[tid] + (tid >= 32 ? wc[0] : 0)] = tid;
    if (tid == 0) g_cnt[blockIdx.x] = act;
    __syncthreads();

    {
        float lw0 = lnw[lane], lw1 = lnw[lane+32];
        float lb0 = lnb[lane], lb1 = lnb[lane+32];
        for (int ci = warp; ci < act; ci += 8) {
            int r = cmap[ci];
            const float* src = inputs + (row0 + r)*64;
            float v0 = src[lane], v1 = src[lane+32];
            float s = v0 + v1;
            #pragma unroll
            for (int o = 16; o; o >>= 1) s += __shfl_xor_sync(~0u, s, o);
            float mu = s * (1.f/64.f);
            float d0 = v0 - mu, d1 = v1 - mu;
            float q = d0*d0 + d1*d1;
            #pragma unroll
            for (int o = 16; o; o >>= 1) q += __shfl_xor_sync(~0u, q, o);
            float rs = rsqrtf(q * (1.f/64.f) + LN_EPS);
            xs[ci*64 + lane]      = d0*rs*lw0 + lb0;
            xs[ci*64 + 32 + lane] = d1*rs*lw1 + lb1;
        }
    }
    __syncthreads();

    int c  = tid & 63;
    int rb = tid >> 6;
    float bkc = bk[c], bvc = bv[c];
    const ulonglong2* xs2 = reinterpret_cast<const ulonglong2*>(xs);
    int G = (act + 31) >> 5;
    for (int g = 0; g < G; ++g) {
        ull ak[8], av[8];
        #pragma unroll
        for (int t = 0; t < 8; ++t) { ak[t] = 0ull; av[t] = 0ull; }
        #pragma unroll
        for (int d4 = 0; d4 < 16; ++d4) {
            ulonglong2 wk = __ldg(g_wk2v + d4*64 + c);
            ulonglong2 wv = __ldg(g_wv2v + d4*64 + c);
            #pragma unroll
            for (int t = 0; t < 8; ++t) {
                int ci = g*32 + rb + 4*t;
                ulonglong2 x = xs2[ci*16 + d4];
                ak[t] = ffma2(x.x, wk.x, ak[t]);
                ak[t] = ffma2(x.y, wk.y, ak[t]);
                av[t] = ffma2(x.x, wv.x, av[t]);
                av[t] = ffma2(x.y, wv.y, av[t]);
            }
        }
        #pragma unroll
        for (int t = 0; t < 8; ++t) {
            int ci = g*32 + rb + 4*t;
            if (ci < act) {
                float2 k2 = unpackf2(ak[t]);
                float2 v2 = unpackf2(av[t]);
                g_k[(row0 + ci)*64 + c] = k2.x + k2.y + bkc;
                g_v[(row0 + ci)*64 + c] = v2.x + v2.y + bvc;
            }
        }
    }
    // rows [act, pad8) never written -> stay zero (bss), safe for padded attn loops
}

// ---------------- LN over slot rows ----------------
__device__ __forceinline__ void lnrows(const float* in, float* out,
                                       const float* __restrict__ w,
                                       const float* __restrict__ bia, int tid, int nrows) {
    int wp = tid >> 5, lane = tid & 31;
    if (wp >= nrows) return;
    const float* p = in + wp*64;
    float v0 = p[lane], v1 = p[lane+32];
    float s = v0 + v1;
    #pragma unroll
    for (int o = 16; o; o >>= 1) s += __shfl_xor_sync(~0u, s, o);
    float mu = s * (1.f/64.f);
    float d0 = v0 - mu, d1 = v1 - mu;
    float q = d0*d0 + d1*d1;
    #pragma unroll
    for (int o = 16; o; o >>= 1) q += __shfl_xor_sync(~0u, q, o);
    float rs = rsqrtf(q * (1.f/64.f) + LN_EPS);
    out[wp*64 + lane]      = d0*rs*w[lane] + bia[lane];
    out[wp*64 + lane + 32] = d1*rs*w[lane+32] + bia[lane+32];
}

// ---------------- init ----------------
__global__ __launch_bounds__(256)
void k_init(const float* __restrict__ noise, const float* __restrict__ mu,
            const float* __restrict__ sg,
            const float* __restrict__ ln_s_w, const float* __restrict__ ln_s_b,
            const float* __restrict__ bq) {
    __shared__ float sl[512], sn[512];
    int b = blockIdx.x, tid = threadIdx.x;
    #pragma unroll
    for (int u = 0; u < 2; ++u) {
        int t = tid + 256*u, dd = t & 63;
        float s = mu[dd] + sg[dd]*noise[b*512 + t];
        sl[t] = s;
        g_slots[b*512 + t] = s;
    }
    __syncthreads();
    lnrows(sl, sn, ln_s_w, ln_s_b, tid, 8);
    __syncthreads();
    #pragma unroll
    for (int u = 0; u < 2; ++u) {
        int t = tid + 256*u, j = t >> 6, dd = t & 63;
        float acc = bq[dd];
        const float2* sj2 = (const float2*)(sn + j*64);
        #pragma unroll 8
        for (int d2 = 0; d2 < 32; ++d2) {
            float2 w = g_Wqp[d2*64 + dd];
            float2 s2 = sj2[d2];
            acc += s2.x*w.x + s2.y*w.y;
        }
        g_q[b*512 + t] = acc * SCALE;
    }
}

// ---------------- attention: fp32 k/v with f32x2 math, in-thread softmax ----------------
__global__ __launch_bounds__(256)
void k_attn() {
    __shared__ float dots[8*DSTR];
    __shared__ float att[8*DSTR];
    __shared__ float redP[8*512];
    __shared__ float redS[64];
    __shared__ int   cnts[4];

    int b = blockIdx.y, chunk = blockIdx.x;
    int tid = threadIdx.x;
    int warp = tid >> 5, lane = tid & 31;
    int jj = lane & 7;
    int gg = lane >> 3;

    if (tid < 4) cnts[tid] = g_cnt[b*(N/TILE_R) + chunk*4 + tid];

    ull q2[8];
    {
        const float4* qp = (const float4*)(g_q + b*512 + jj*64) + (gg << 2);
        #pragma unroll
        for (int i = 0; i < 4; ++i) {
            float4 t4 = qp[i];
            q2[2*i]   = packf2(t4.x, t4.y);
            q2[2*i+1] = packf2(t4.z, t4.w);
        }
    }
    __syncthreads();

    // Phase A: dots via f32x2
    #pragma unroll
    for (int s = 0; s < 4; ++s) {
        int nit = (cnts[s] + 7) >> 3;
        const float* kb = g_k + ((size_t)(b*(N/TILE_R) + chunk*4 + s) * TILE_R) * 64;
        #pragma unroll 2
        for (int it = 0; it < nit; ++it) {
            int r = it*8 + warp;
            const ulonglong2* kp = (const ulonglong2*)(kb + r*64) + (gg << 2);
            ulonglong2 x0 = kp[0], x1 = kp[1], x2 = kp[2], x3 = kp[3];
            ull acc = 0ull;
            acc = ffma2(x0.x, q2[0], acc); acc = ffma2(x0.y, q2[1], acc);
            acc = ffma2(x1.x, q2[2], acc); acc = ffma2(x1.y, q2[3], acc);
            acc = ffma2(x2.x, q2[4], acc); acc = ffma2(x2.y, q2[5], acc);
            acc = ffma2(x3.x, q2[6], acc); acc = ffma2(x3.y, q2[7], acc);
            float2 f = unpackf2(acc);
            float d = f.x + f.y;
            d += __shfl_xor_sync(~0u, d, 8);
            d += __shfl_xor_sync(~0u, d, 16);
            if (gg == 0) dots[jj*DSTR + s*64 + r] = d;
        }
    }
    __syncthreads();

    // Phase B: in-thread softmax, zero att on pad rows
    {
        int s = tid >> 6, r = tid & 63;
        int act = cnts[s];
        int pad8 = (act + 7) & ~7;
        if (r < act) {
            float d[8];
            #pragma unroll
            for (int j = 0; j < 8; ++j) d[j] = dots[j*DSTR + tid];
            float m = d[0];
            #pragma unroll
            for (int j = 1; j < 8; ++j) m = fmaxf(m, d[j]);
            float e[8], sum = 0.f;
            #pragma unroll
            for (int j = 0; j < 8; ++j) { e[j] = __expf(d[j] - m); sum += e[j]; }
            float inv = __fdividef(1.f, sum);
            #pragma unroll
            for (int j = 0; j < 8; ++j) att[j*DSTR + tid] = e[j]*inv + EPSA;
        } else if (r < pad8) {
            #pragma unroll
            for (int j = 0; j < 8; ++j) att[j*DSTR + tid] = 0.f;
        }
    }
    __syncthreads();

    // Phase C: P accumulation via f32x2
    ull P2[8];
    #pragma unroll
    for (int i = 0; i < 8; ++i) P2[i] = 0ull;
    float S = 0.f;
    #pragma unroll
    for (int s = 0; s < 4; ++s) {
        int nit = (cnts[s] + 7) >> 3;
        const float* vb = g_v + ((size_t)(b*(N/TILE_R) + chunk*4 + s) * TILE_R) * 64;
        #pragma unroll 2
        for (int it = 0; it < nit; ++it) {
            int r = it*8 + warp;
            float a = att[jj*DSTR + s*64 + r];
            S += a;
            ull a2 = packf2(a, a);
            const ulonglong2* vp = (const ulonglong2*)(vb + r*64) + (gg << 2);
            ulonglong2 x0 = vp[0], x1 = vp[1], x2 = vp[2], x3 = vp[3];
            P2[0] = ffma2(x0.x, a2, P2[0]); P2[1] = ffma2(x0.y, a2, P2[1]);
            P2[2] = ffma2(x1.x, a2, P2[2]); P2[3] = ffma2(x1.y, a2, P2[3]);
            P2[4] = ffma2(x2.x, a2, P2[4]); P2[5] = ffma2(x2.y, a2, P2[5]);
            P2[6] = ffma2(x3.x, a2, P2[6]); P2[7] = ffma2(x3.y, a2, P2[7]);
        }
    }

    float* rp = redP + warp*512 + jj*64 + (gg << 4);
    #pragma unroll
    for (int i = 0; i < 4; ++i) {
        float2 f0 = unpackf2(P2[2*i]), f1 = unpackf2(P2[2*i+1]);
        *(float4*)(rp + 4*i) = make_float4(f0.x, f0.y, f1.x, f1.y);
    }
    if (gg == 0) redS[warp*8 + jj] = S;
    __syncthreads();

    #pragma unroll
    for (int u = 0; u < 2; ++u) {
        int t = tid + 256*u;
        float s = 0.f;
        #pragma unroll
        for (int w = 0; w < 8; ++w) s += redP[w*512 + t];
        g_Pp[((size_t)b*NB + chunk)*512 + t] = s;
    }
    if (tid < 8) {
        float s = 0.f;
        #pragma unroll
        for (int w = 0; w < 8; ++w) s += redS[w*8 + tid];
        g_Sp[(b*NB + chunk)*8 + tid] = s;
    }
}

// ---------------- slot update: GRU + residual MLP (+ next q); 4 slots/block ----------------
__global__ __launch_bounds__(256)
void k_update(const float* __restrict__ b_ih, const float* __restrict__ b_hh,
              const float* __restrict__ b1, const float* __restrict__ b2,
              const float* __restrict__ ln_ff_w, const float* __restrict__ ln_ff_b,
              const float* __restrict__ ln_s_w, const float* __restrict__ ln_s_b,
              const float* __restrict__ bq,
              float* __restrict__ d_out, int last) {
    __shared__ float upd[256], prev[256], snew[256], ffs[256], hid[512], sfin[256], Ssm[4];
    int b = blockIdx.y, half = blockIdx.x, tid = threadIdx.x;
    int j0 = half * 4;
    int j = tid >> 6, dd = tid & 63;
    int J = j0 + j;

    if (tid < 4) {
        float s = 0.f;
        const float* sp = g_Sp + b*NB*8 + j0 + tid;
        #pragma unroll
        for (int p = 0; p < NB; ++p) s += sp[p*8];
        Ssm[tid] = s;
    }
    float pr;
    {
        float s = 0.f;
        const float* pp = g_Pp + (size_t)b*NB*512 + J*64 + dd;
        #pragma unroll
        for (int p = 0; p < NB; ++p) s += pp[p*512];
        pr = s;
        prev[tid] = g_slots[b*512 + J*64 + dd];
    }
    __syncthreads();
    upd[tid] = pr / Ssm[j];
    __syncthreads();

    // GRU with packed weights
    {
        const float* uj = upd + j*64;
        const float* hj = prev + j*64;
        float xr = b_ih[dd], xz = b_ih[64+dd], xn = b_ih[128+dd];
        float hr = b_hh[dd], hz = b_hh[64+dd], hn = b_hh[128+dd];
        #pragma unroll 8
        for (int d = 0; d < 64; ++d) {
            float uu = uj[d], hh = hj[d];
            float4 wa = __ldg(g_WgA + d*64 + dd);
            float2 wb = __ldg(g_WgB + d*64 + dd);
            xr += uu*wa.x; xz += uu*wa.y; xn += uu*wa.z;
            hr += hh*wa.w; hz += hh*wb.x; hn += hh*wb.y;
        }
        float rg = 1.f/(1.f + __expf(-(xr + hr)));
        float zg = 1.f/(1.f + __expf(-(xz + hz)));
        float t2 = __expf(2.f*(xn + rg*hn));
        float nn = 1.f - 2.f/(t2 + 1.f);
        snew[tid] = (1.f - zg)*nn + zg*prev[tid];
    }
    __syncthreads();
    lnrows(snew, ffs, ln_ff_w, ln_ff_b, tid, 4);
    __syncthreads();
    // MLP layer 1
    {
        int h2 = dd;
        float a0 = b1[2*h2], a1 = b1[2*h2+1];
        const float* fj = ffs + j*64;
        #pragma unroll 8
        for (int d = 0; d < 64; ++d) {
            float2 w = __ldg(g_W1p + d*64 + h2);
            float f = fj[d];
            a0 += f*w.x; a1 += f*w.y;
        }
        hid[j*128 + 2*h2]   = fmaxf(a0, 0.f);
        hid[j*128 + 2*h2+1] = fmaxf(a1, 0.f);
    }
    __syncthreads();
    {
        float acc = b2[dd];
        const float2* hj2 = (const float2*)(hid + j*128);
        #pragma unroll 8
        for (int h2 = 0; h2 < 64; ++h2) {
            float2 w = __ldg(g_W2p + h2*64 + dd);
            float2 hv = hj2[h2];
            acc += hv.x*w.x + hv.y*w.y;
        }
        float o = snew[tid] + acc;
        sfin[tid] = o;
        g_slots[b*512 + J*64 + dd] = o;
        if (last) d_out[b*512 + J*64 + dd] = o;
    }
    if (!last) {
        __syncthreads();
        lnrows(sfin, ffs, ln_s_w, ln_s_b, tid, 4);
        __syncthreads();
        {
            float acc = bq[dd];
            const float2* sj2 = (const float2*)(ffs + j*64);
            #pragma unroll 8
            for (int d2 = 0; d2 < 32; ++d2) {
                float2 w = __ldg(g_Wqp + d2*64 + dd);
                float2 s2 = sj2[d2];
                acc += s2.x*w.x + s2.y*w.y;
            }
            g_q[b*512 + J*64 + dd] = acc * SCALE;
        }
    }
}

// ---------------- launch ----------------
extern "C" void kernel_launch(void* const* d_in, const int* in_sizes, int n_in,
                              void* d_out, int out_size) {
    const float* inputs     = (const float*)d_in[0];
    const int*   mask       = (const int*)  d_in[1];
    const float* noise      = (const float*)d_in[2];
    const float* slots_mu   = (const float*)d_in[3];
    const float* slots_sig  = (const float*)d_in[4];
    const float* Wq         = (const float*)d_in[5];
    const float* bq         = (const float*)d_in[6];
    const float* Wk         = (const float*)d_in[7];
    const float* bk         = (const float*)d_in[8];
    const float* Wv         = (const float*)d_in[9];
    const float* bv         = (const float*)d_in[10];
    const float* W_ih       = (const float*)d_in[11];
    const float* b_ih       = (const float*)d_in[12];
    const float* W_hh       = (const float*)d_in[13];
    const float* b_hh       = (const float*)d_in[14];
    const float* W1         = (const float*)d_in[15];
    const float* b1         = (const float*)d_in[16];
    const float* W2         = (const float*)d_in[17];
    const float* b2         = (const float*)d_in[18];
    const float* ln_in_w    = (const float*)d_in[19];
    const float* ln_in_b    = (const float*)d_in[20];
    const float* ln_s_w     = (const float*)d_in[21];
    const float* ln_s_b     = (const float*)d_in[22];
    const float* ln_ff_w    = (const float*)d_in[23];
    const float* ln_ff_b    = (const float*)d_in[24];
    float* out = (float*)d_out;

    k_prep<<<48, 256>>>(Wk, Wv, W_ih, W_hh, W1, W2, Wq);
    k_ln_kv<<<(B*N)/TILE_R, 256>>>(inputs, mask, bk, bv, ln_in_w, ln_in_b);
    k_init<<<B, 256>>>(noise, slots_mu, slots_sig, ln_s_w, ln_s_b, bq);
    for (int it = 0; it < ITERS; ++it) {
        k_attn<<<dim3(NB, B), 256>>>();
        k_update<<<dim3(2, B), 256>>>(b_ih, b_hh, b1, b2, ln_ff_w, ln_ff_b,
                                      ln_s_w, ln_s_b, bq, out, it == ITERS-1 ? 1 : 0);
    }
}